// round 1
// baseline (speedup 1.0000x reference)
#include <cuda_runtime.h>

#define B_ROWS 32768
#define K_DIM  512
#define N_DIM  2048
#define VBS    256
#define NVB    128   // B_ROWS / VBS

// Scratch: GEMM output + folded BN affine (scale/shift per (virtual batch, col))
__device__ float g_Y[(size_t)B_ROWS * N_DIM];
__device__ float g_scale[NVB * N_DIM];
__device__ float g_shift[NVB * N_DIM];

// ---------------------------------------------------------------------------
// Kernel 1: fp32 GEMM  Y[m,n] = sum_k A[m,k] * W[n,k]
// A: [32768,512] row-major, W: [2048,512] row-major (both K-contiguous).
// Tiles 128x128x16, 256 threads, 8x8 per-thread micro-tile.
// ---------------------------------------------------------------------------
#define BM 128
#define BN 128
#define BK 16

__global__ __launch_bounds__(256)
void gemm_f32(const float* __restrict__ A, const float* __restrict__ W) {
    __shared__ float As[BK][BM];
    __shared__ float Bs[BK][BN];

    const int bm  = blockIdx.y * BM;
    const int bn  = blockIdx.x * BN;
    const int tid = threadIdx.x;
    const int tx  = tid & 15;
    const int ty  = tid >> 4;

    float acc[8][8];
    #pragma unroll
    for (int i = 0; i < 8; i++)
        #pragma unroll
        for (int j = 0; j < 8; j++) acc[i][j] = 0.f;

    for (int k0 = 0; k0 < K_DIM; k0 += BK) {
        // Load 128x16 tiles of A and W, stored transposed [BK][BM] in smem.
        #pragma unroll
        for (int l = 0; l < 2; l++) {
            int lin = tid + l * 256;       // 0..511 (float4 units)
            int row = lin >> 2;            // 0..127
            int kc  = (lin & 3) << 2;      // 0,4,8,12
            float4 va = *(const float4*)(A + (size_t)(bm + row) * K_DIM + k0 + kc);
            As[kc + 0][row] = va.x;
            As[kc + 1][row] = va.y;
            As[kc + 2][row] = va.z;
            As[kc + 3][row] = va.w;
            float4 vb = *(const float4*)(W + (size_t)(bn + row) * K_DIM + k0 + kc);
            Bs[kc + 0][row] = vb.x;
            Bs[kc + 1][row] = vb.y;
            Bs[kc + 2][row] = vb.z;
            Bs[kc + 3][row] = vb.w;
        }
        __syncthreads();

        #pragma unroll
        for (int kk = 0; kk < BK; kk++) {
            float a[8], b[8];
            *(float4*)(a)     = *(const float4*)(&As[kk][ty * 8]);
            *(float4*)(a + 4) = *(const float4*)(&As[kk][ty * 8 + 4]);
            *(float4*)(b)     = *(const float4*)(&Bs[kk][tx * 8]);
            *(float4*)(b + 4) = *(const float4*)(&Bs[kk][tx * 8 + 4]);
            #pragma unroll
            for (int i = 0; i < 8; i++)
                #pragma unroll
                for (int j = 0; j < 8; j++)
                    acc[i][j] = fmaf(a[i], b[j], acc[i][j]);
        }
        __syncthreads();
    }

    #pragma unroll
    for (int i = 0; i < 8; i++) {
        float* yp = g_Y + (size_t)(bm + ty * 8 + i) * N_DIM + bn + tx * 8;
        *(float4*)(yp)     = make_float4(acc[i][0], acc[i][1], acc[i][2], acc[i][3]);
        *(float4*)(yp + 4) = make_float4(acc[i][4], acc[i][5], acc[i][6], acc[i][7]);
    }
}

// ---------------------------------------------------------------------------
// Kernel 2: GhostBatchNorm statistics per (virtual batch, column).
// Folds gamma/beta: out = y*scale + shift with
//   scale = gamma * rsqrt(var + eps), shift = beta - mean*scale
// ---------------------------------------------------------------------------
__global__ __launch_bounds__(256)
void bn_stats(const float* __restrict__ gamma, const float* __restrict__ beta) {
    const int d  = blockIdx.x * 256 + threadIdx.x;  // column
    const int vb = blockIdx.y;                      // virtual batch
    const float* p = g_Y + (size_t)vb * VBS * N_DIM + d;

    float s = 0.f, s2 = 0.f;
    #pragma unroll 8
    for (int r = 0; r < VBS; r++) {
        float v = p[(size_t)r * N_DIM];
        s  += v;
        s2  = fmaf(v, v, s2);
    }
    float mean = s * (1.f / VBS);
    float var  = s2 * (1.f / VBS) - mean * mean;   // biased var, matches BN training
    float sc   = gamma[d] * rsqrtf(var + 1e-5f);
    g_scale[vb * N_DIM + d] = sc;
    g_shift[vb * N_DIM + d] = fmaf(-mean, sc, beta[d]);
}

// ---------------------------------------------------------------------------
// Kernel 3: fused normalize + prior scaling + exact sparsemax per row.
// One CTA per row (2048 cols), 8 cols/thread held in registers.
// Sparsemax threshold via Michelot's algorithm (exact finite convergence):
//   support = all; repeat: tau = (sum_{z>tau} z - 1)/|{z>tau}| until stable.
// ---------------------------------------------------------------------------
__global__ __launch_bounds__(256)
void sparsemax_fused(const float* __restrict__ priors, float* __restrict__ out) {
    const int row = blockIdx.x;
    const int vb  = row >> 8;          // row / VBS
    const int t   = threadIdx.x;
    const int c0  = t * 8;

    __shared__ float warp_s[8];
    __shared__ float warp_c[8];
    __shared__ float bcast[2];

    const float* yrow = g_Y    + (size_t)row * N_DIM;
    const float* prow = priors + (size_t)row * N_DIM;
    const float* scr  = g_scale + (size_t)vb * N_DIM;
    const float* shr  = g_shift + (size_t)vb * N_DIM;

    float z[8];
    #pragma unroll
    for (int v = 0; v < 2; v++) {
        float4 y  = *(const float4*)(yrow + c0 + v * 4);
        float4 p  = *(const float4*)(prow + c0 + v * 4);
        float4 sc = *(const float4*)(scr  + c0 + v * 4);
        float4 sh = *(const float4*)(shr  + c0 + v * 4);
        z[v * 4 + 0] = fmaf(y.x, sc.x, sh.x) * p.x;
        z[v * 4 + 1] = fmaf(y.y, sc.y, sh.y) * p.y;
        z[v * 4 + 2] = fmaf(y.z, sc.z, sh.z) * p.z;
        z[v * 4 + 3] = fmaf(y.w, sc.w, sh.w) * p.w;
    }

    // --- block reduction helper (sum + count), inlined twice below ---
    // initial tau: support = everything
    float ls = 0.f, lc = 0.f;
    #pragma unroll
    for (int i = 0; i < 8; i++) ls += z[i];
    // reduce ls (count unused on first pass)
    #pragma unroll
    for (int o = 16; o; o >>= 1) ls += __shfl_down_sync(0xffffffffu, ls, o);
    if ((t & 31) == 0) warp_s[t >> 5] = ls;
    __syncthreads();
    if (t < 32) {
        float s = (t < 8) ? warp_s[t] : 0.f;
        #pragma unroll
        for (int o = 4; o; o >>= 1) s += __shfl_down_sync(0xffffffffu, s, o);
        if (t == 0) bcast[0] = s;
    }
    __syncthreads();
    float tau   = (bcast[0] - 1.f) * (1.f / (float)N_DIM);
    float kprev = (float)N_DIM;
    __syncthreads();

    for (int it = 0; it < 64; it++) {
        ls = 0.f; lc = 0.f;
        #pragma unroll
        for (int i = 0; i < 8; i++) {
            if (z[i] > tau) { ls += z[i]; lc += 1.f; }
        }
        #pragma unroll
        for (int o = 16; o; o >>= 1) {
            ls += __shfl_down_sync(0xffffffffu, ls, o);
            lc += __shfl_down_sync(0xffffffffu, lc, o);
        }
        if ((t & 31) == 0) { warp_s[t >> 5] = ls; warp_c[t >> 5] = lc; }
        __syncthreads();
        if (t < 32) {
            float s = (t < 8) ? warp_s[t] : 0.f;
            float c = (t < 8) ? warp_c[t] : 0.f;
            #pragma unroll
            for (int o = 4; o; o >>= 1) {
                s += __shfl_down_sync(0xffffffffu, s, o);
                c += __shfl_down_sync(0xffffffffu, c, o);
            }
            if (t == 0) { bcast[0] = s; bcast[1] = c; }
        }
        __syncthreads();
        float S = bcast[0];
        float C = bcast[1];
        __syncthreads();
        if (C == kprev) break;          // support stable -> tau is exact
        tau   = (S - 1.f) / C;
        kprev = C;
    }

    float o0[8];
    #pragma unroll
    for (int i = 0; i < 8; i++) o0[i] = fmaxf(z[i] - tau, 0.f);
    float* orow = out + (size_t)row * N_DIM + c0;
    *(float4*)(orow)     = make_float4(o0[0], o0[1], o0[2], o0[3]);
    *(float4*)(orow + 4) = make_float4(o0[4], o0[5], o0[6], o0[7]);
}

// ---------------------------------------------------------------------------
extern "C" void kernel_launch(void* const* d_in, const int* in_sizes, int n_in,
                              void* d_out, int out_size) {
    const float* priors = (const float*)d_in[0];   // [32768, 2048]
    const float* feat   = (const float*)d_in[1];   // [32768, 512]
    const float* W      = (const float*)d_in[2];   // [2048, 512]
    const float* gamma  = (const float*)d_in[3];   // [2048]
    const float* beta   = (const float*)d_in[4];   // [2048]
    float* out = (float*)d_out;                    // [32768, 2048]

    dim3 ggrid(N_DIM / BN, B_ROWS / BM);           // (16, 256)
    gemm_f32<<<ggrid, 256>>>(feat, W);

    dim3 sgrid(N_DIM / 256, NVB);                  // (8, 128)
    bn_stats<<<sgrid, 256>>>(gamma, beta);

    sparsemax_fused<<<B_ROWS, 256>>>(priors, out);
}